// round 14
// baseline (speedup 1.0000x reference)
#include <cuda_runtime.h>
#include <math.h>

#define Bz   16
#define CN   22
#define T    1000
#define EXPD 300
#define FCH  150
#define C3   450
#define SPD  100
#define NCLS 4
#define NFLAT 5050
#define PITCH 102     // float2-aligned row pitch; cols 100,101 are zero pad
#define NSWEEP 9
#define HALO 40
#define JT   800      // 50 half-warp PEs

// ---------------- scratch (device globals; no runtime alloc) ----------------
__device__ float g_W[C3 * CN];
__device__ float g_H1[Bz * C3 * T];
__device__ float g_H2[Bz * C3 * T];
__device__ float g_S[Bz * SPD * T];
__device__ float g_mean[Bz * SPD];
__device__ float g_cov[Bz * SPD * SPD];
__device__ float g_tmp[Bz * SPD * SPD];
__device__ float g_P[Bz * SPD * SPD];

// ---------------- K1: collapse block 1-4 linear ops into (150x22) ----------------
__global__ void k_prep(const float* __restrict__ w1, const float* __restrict__ w2,
                       const float* __restrict__ w3, const float* __restrict__ w4,
                       int seg) {
    __shared__ float scale[EXPD];
    __shared__ float A1[FCH * CN];
    int tid = threadIdx.x;
    for (int e = tid; e < EXPD; e += blockDim.x) {
        float s = 0.f;
        for (int c = 0; c < CN; c++) { float v = w3[e * CN + c]; s += v * v; }
        float n = sqrtf(s);
        scale[e] = w2[e] * fminf(1.0f, 1.0f / (n + 1e-12f));
    }
    __syncthreads();
    for (int idx = tid; idx < FCH * CN; idx += blockDim.x) {
        int f = idx / CN, c = idx % CN;
        float s = 0.f;
        for (int e = 0; e < EXPD; e++) s += w4[f * EXPD + e] * scale[e] * w3[e * CN + c];
        A1[idx] = s;
    }
    __syncthreads();
    float w10 = w1[0], w11 = w1[1], w12 = w1[2];
    for (int idx = tid; idx < FCH * CN; idx += blockDim.x) {
        int f = idx / CN, cp = idx % CN;
        float s = 0.f;
        int c;
        c = cp + 1; if (c < CN)           s += w10 * A1[f * CN + c];
        c = cp;                            s += w11 * A1[f * CN + c];
        c = cp - 1; if (c >= 0)           s += w12 * A1[f * CN + c];
        g_W[seg * FCH * CN + idx] = s;
    }
}

// ---------------- K2: H1 = Wstack(450x22) @ x per batch (f-split x3) ----------------
__global__ void k_gemm1(const float* __restrict__ x) {
    __shared__ float sW[FCH * CN];
    int tx = threadIdx.x;
    int b  = blockIdx.y;
    int f0 = blockIdx.z * FCH;
    int t  = blockIdx.x * 128 + tx;
    for (int idx = tx; idx < FCH * CN; idx += 128) sW[idx] = g_W[f0 * CN + idx];
    float xr[CN];
    #pragma unroll
    for (int c = 0; c < CN; c++)
        xr[c] = (t < T) ? x[((size_t)b * CN + c) * T + t] : 0.f;
    __syncthreads();
    if (t < T) {
        for (int f = 0; f < FCH; f++) {
            const float* w = &sW[f * CN];
            float a0 = 0.f, a1 = 0.f;
            #pragma unroll
            for (int c = 0; c < CN; c += 2) { a0 += w[c] * xr[c]; a1 += w[c + 1] * xr[c + 1]; }
            g_H1[((size_t)b * C3 + f0 + f) * T + t] = a0 + a1;
        }
    }
}

// ---------------- K3: fused LN -> depthwise temporal conv -> LN per row ----------------
__global__ void k_tail(
    const float* g1_0, const float* b1_0, const float* w5_0, const float* g2_0, const float* b2_0,
    const float* g1_1, const float* b1_1, const float* w5_1, const float* g2_1, const float* b2_1,
    const float* g1_2, const float* b1_2, const float* w5_2, const float* g2_2, const float* b2_2)
{
    __shared__ float buf1[T + 2 * HALO];
    __shared__ float buf2[T];
    __shared__ float sw5[80];
    __shared__ float redA[256], redB[256];
    __shared__ float s_mean, s_rstd;
    int row = blockIdx.x;
    int ch  = row % C3;
    int seg = ch / FCH, fl = ch % FCH;
    const float *g1, *b1, *w5, *g2, *b2; int K;
    if (seg == 0)      { g1 = g1_0; b1 = b1_0; w5 = w5_0; g2 = g2_0; b2 = b2_0; K = 15; }
    else if (seg == 1) { g1 = g1_1; b1 = b1_1; w5 = w5_1; g2 = g2_1; b2 = b2_1; K = 75; }
    else               { g1 = g1_2; b1 = b1_2; w5 = w5_2; g2 = g2_2; b2 = b2_2; K = 55; }
    const float* in = g_H1 + (size_t)row * T;
    float* out = g_H2 + (size_t)row * T;
    int tid = threadIdx.x;

    if (tid < HALO) { buf1[tid] = 0.f; buf1[T + HALO + tid] = 0.f; }
    float s = 0.f, s2 = 0.f;
    for (int t = tid; t < T; t += 256) { float v = in[t]; buf1[HALO + t] = v; s += v; s2 += v * v; }
    redA[tid] = s; redB[tid] = s2; __syncthreads();
    for (int st = 128; st > 0; st >>= 1) {
        if (tid < st) { redA[tid] += redA[tid + st]; redB[tid] += redB[tid + st]; }
        __syncthreads();
    }
    if (tid == 0) {
        float m = redA[0] * (1.f / T); s_mean = m;
        s_rstd = rsqrtf(redB[0] * (1.f / T) - m * m + 1e-5f);
    }
    if (tid < K) sw5[tid] = w5[fl * K + tid];
    __syncthreads();
    float m = s_mean, r = s_rstd;
    for (int t = tid; t < T; t += 256) buf1[HALO + t] = (buf1[HALO + t] - m) * r * g1[t] + b1[t];
    __syncthreads();
    int pad = K / 2;
    for (int t = tid; t < T; t += 256) {
        float acc = 0.f;
        const float* src = &buf1[HALO + t - pad];
        for (int k = 0; k < K; k++) acc += src[k] * sw5[k];
        buf2[t] = acc;
    }
    __syncthreads();
    s = 0.f; s2 = 0.f;
    for (int t = tid; t < T; t += 256) { float v = buf2[t]; s += v; s2 += v * v; }
    redA[tid] = s; redB[tid] = s2; __syncthreads();
    for (int st = 128; st > 0; st >>= 1) {
        if (tid < st) { redA[tid] += redA[tid + st]; redB[tid] += redB[tid + st]; }
        __syncthreads();
    }
    if (tid == 0) {
        float mm = redA[0] * (1.f / T); s_mean = mm;
        s_rstd = rsqrtf(redB[0] * (1.f / T) - mm * mm + 1e-5f);
    }
    __syncthreads();
    m = s_mean; r = s_rstd;
    for (int t = tid; t < T; t += 256) out[t] = (buf2[t] - m) * r * g2[t] + b2[t];
}

// ---------------- K4: S = w_sconv(100x450) @ H2 per batch ----------------
__global__ void k_sconv(const float* __restrict__ w_sconv) {
    __shared__ float sH[45 * 128];
    __shared__ float sW[SPD * 45];
    int tid = threadIdx.x;
    int tx = tid & 127, ig = tid >> 7;
    int t0 = blockIdx.x * 128, b = blockIdx.y;
    float acc[25];
    #pragma unroll
    for (int ii = 0; ii < 25; ii++) acc[ii] = 0.f;
    for (int c0 = 0; c0 < C3; c0 += 45) {
        __syncthreads();
        for (int idx = tid; idx < 45 * 128; idx += 512) {
            int rr = idx >> 7, tt = idx & 127;
            sH[idx] = (t0 + tt < T) ? g_H2[((size_t)b * C3 + c0 + rr) * T + t0 + tt] : 0.f;
        }
        for (int idx = tid; idx < SPD * 45; idx += 512) {
            int i = idx / 45, c = idx % 45;
            sW[idx] = w_sconv[i * C3 + c0 + c];
        }
        __syncthreads();
        for (int c = 0; c < 45; c++) {
            float xv = sH[c * 128 + tx];
            #pragma unroll
            for (int ii = 0; ii < 25; ii++)
                acc[ii] += sW[(ig * 25 + ii) * 45 + c] * xv;
        }
    }
    int t = t0 + tx;
    if (t < T)
        for (int ii = 0; ii < 25; ii++)
            g_S[((size_t)b * SPD + ig * 25 + ii) * T + t] = acc[ii];
}

// ---------------- K5: per-row means of S ----------------
__global__ void k_mean() {
    __shared__ float red[256];
    int row = blockIdx.x;
    const float* in = g_S + (size_t)row * T;
    int tid = threadIdx.x;
    float s = 0.f;
    for (int t = tid; t < T; t += 256) s += in[t];
    red[tid] = s; __syncthreads();
    for (int st = 128; st > 0; st >>= 1) { if (tid < st) red[tid] += red[tid + st]; __syncthreads(); }
    if (tid == 0) g_mean[row] = red[0] * (1.f / T);
}

// ---------------- K6: covariance (tiled SYRK + mean correction + ridge) ----------------
__global__ void k_cov() {
    __shared__ float sA[32 * 51], sB[32 * 51];
    int b = blockIdx.z;
    int it = blockIdx.x * 32, jt = blockIdx.y * 32;
    int tid = threadIdx.x;
    int il = tid >> 4, jl = tid & 15;
    float acc00 = 0.f, acc01 = 0.f, acc10 = 0.f, acc11 = 0.f;
    for (int t0 = 0; t0 < T; t0 += 50) {
        __syncthreads();
        for (int idx = tid; idx < 32 * 50; idx += 256) {
            int rr = idx / 50, tt = idx % 50;
            int gi = it + rr;
            sA[rr * 51 + tt] = (gi < SPD) ? g_S[((size_t)b * SPD + gi) * T + t0 + tt] : 0.f;
            int gj = jt + rr;
            sB[rr * 51 + tt] = (gj < SPD) ? g_S[((size_t)b * SPD + gj) * T + t0 + tt] : 0.f;
        }
        __syncthreads();
        for (int tt = 0; tt < 50; tt++) {
            float a0 = sA[(il * 2) * 51 + tt], a1 = sA[(il * 2 + 1) * 51 + tt];
            float b0 = sB[(jl * 2) * 51 + tt], b1 = sB[(jl * 2 + 1) * 51 + tt];
            acc00 += a0 * b0; acc01 += a0 * b1; acc10 += a1 * b0; acc11 += a1 * b1;
        }
    }
    float accs[2][2] = {{acc00, acc01}, {acc10, acc11}};
    for (int di = 0; di < 2; di++)
        for (int dj = 0; dj < 2; dj++) {
            int i = it + il * 2 + di, j = jt + jl * 2 + dj;
            if (i < SPD && j < SPD) {
                float v = (accs[di][dj] - (float)T * g_mean[b * SPD + i] * g_mean[b * SPD + j]) * (1.f / (T - 1));
                if (i == j) v += 1e-4f;
                g_cov[((size_t)b * SPD + i) * SPD + j] = v;
            }
        }
}

// ---------------- K7/K8: affine congruence P = W C W^T ----------------
__global__ void k_aff1(const float* __restrict__ w_aff) {
    int b = blockIdx.x;
    int o = blockIdx.y * 256 + threadIdx.x;
    if (o >= SPD * SPD) return;
    int i = o / SPD, k = o % SPD;
    float s = 0.f;
    for (int j = 0; j < SPD; j++) s += w_aff[i * SPD + j] * g_cov[((size_t)b * SPD + j) * SPD + k];
    g_tmp[(size_t)b * SPD * SPD + o] = s;
}
__global__ void k_aff2(const float* __restrict__ w_aff) {
    int b = blockIdx.x;
    int o = blockIdx.y * 256 + threadIdx.x;
    if (o >= SPD * SPD) return;
    int i = o / SPD, l = o % SPD;
    float s = 0.f;
    for (int k = 0; k < SPD; k++) s += g_tmp[((size_t)b * SPD + i) * SPD + k] * w_aff[l * SPD + k];
    g_P[(size_t)b * SPD * SPD + o] = s;
}

// ---------------- K9: SYSTOLIC one-sided Jacobi: register-resident rows, ring exchange ----------------
// PE = half-warp (50 PEs). PE i holds rows (top, bot) in registers.
// Round: rotate (top,bot) in regs; ring-shift one hop (Brent-Luk round robin, top_0 fixed).
// Intra-warp hops via shfl.xor(16); cross-warp hops via double-buffered smem slots.
__global__ __launch_bounds__(JT, 1) void k_jacobi(float* __restrict__ out_flat) {
    extern __shared__ float sh[];
    float* W   = sh;                       // SPD*PITCH: staging during sweeps, rows at end
    float* G   = W + SPD * PITCH;          // SPD*PITCH
    float* lwf = G + SPD * PITCH;          // 128
    int b = blockIdx.x, tid = threadIdx.x;
    const int pe  = tid >> 4;              // 0..49
    const int l16 = tid & 15;
    const bool odd = (pe & 1) != 0;
    const bool g3  = (l16 < 3);            // float2 idx 48+l16 valid (48,49,50)

    // Load rows from gmem straight into registers.
    // ta = row pe, tb = row 50+pe. lane l16 holds float2 cols {l16,16+l16,32+l16,48+l16}.
    float2 ta[4], tb[4];
    {
        const float* Rp = g_P + (size_t)b * SPD * SPD + (size_t)pe * SPD;
        const float* Rq = g_P + (size_t)b * SPD * SPD + (size_t)(50 + pe) * SPD;
        #pragma unroll
        for (int t = 0; t < 4; t++) {
            int c = l16 + 16 * t;
            if (c < 50) {
                ta[t] = make_float2(Rp[2 * c], Rp[2 * c + 1]);
                tb[t] = make_float2(Rq[2 * c], Rq[2 * c + 1]);
            } else {
                ta[t] = make_float2(0.f, 0.f);
                tb[t] = make_float2(0.f, 0.f);
            }
        }
    }
    __syncthreads();

    const int NR = NSWEEP * (SPD - 1);
    for (int r = 0; r < NR; r++) {
        // ---- rotate register pair (ta, tb) ----
        float diff = 0.f, dpq = 0.f;
        #pragma unroll
        for (int t = 0; t < 4; t++) {
            diff += (tb[t].x * tb[t].x - ta[t].x * ta[t].x)
                  + (tb[t].y * tb[t].y - ta[t].y * ta[t].y);
            dpq  += ta[t].x * tb[t].x + ta[t].y * tb[t].y;
        }
        #pragma unroll
        for (int k = 8; k >= 1; k >>= 1) {
            diff += __shfl_xor_sync(0xffffffffu, diff, k, 16);
            dpq  += __shfl_xor_sync(0xffffffffu, dpq, k, 16);
        }
        if (fabsf(dpq) > 1e-30f) {
            float tau = diff / (2.f * dpq);
            float tt = ((tau >= 0.f) ? 1.f : -1.f) / (fabsf(tau) + sqrtf(1.f + tau * tau));
            float c = rsqrtf(1.f + tt * tt), s = tt * c;
            #pragma unroll
            for (int t = 0; t < 4; t++) {
                float2 np, nq;
                np.x = c * ta[t].x - s * tb[t].x; np.y = c * ta[t].y - s * tb[t].y;
                nq.x = s * ta[t].x + c * tb[t].x; nq.y = s * ta[t].y + c * tb[t].y;
                ta[t] = np; tb[t] = nq;
            }
        }

        // ---- ring exchange ----
        // intra-out: even>=2 -> ta ; PE0 -> tb ; odd -> tb
        // smem-out : even 2..48 -> tb ; odd 1..47 -> ta ; PE0, PE49 none
        float2 oi[4];
        bool ev_top = (!odd && pe >= 2);
        #pragma unroll
        for (int t = 0; t < 4; t++) oi[t] = ev_top ? ta[t] : tb[t];

        float2 sv[4];                      // PE49 saves old top
        #pragma unroll
        for (int t = 0; t < 4; t++) sv[t] = ta[t];

        int stage = (r & 1) * 50;
        if ((odd && pe <= 47) || (!odd && pe >= 2)) {
            float2* S = (float2*)(W + (size_t)(stage + pe) * PITCH);
            float2* src = odd ? ta : tb;   // odd sends top(ta), even sends bot(tb)
            S[l16]      = src[0];
            S[16 + l16] = src[1];
            S[32 + l16] = src[2];
            if (g3) S[48 + l16] = src[3];
        }
        __syncthreads();

        // intra-warp swap (both directions at once)
        float2 ii[4];
        #pragma unroll
        for (int t = 0; t < 4; t++) {
            ii[t].x = __shfl_xor_sync(0xffffffffu, oi[t].x, 16);
            ii[t].y = __shfl_xor_sync(0xffffffffu, oi[t].y, 16);
        }

        if (!odd) {
            // new bot = intra-in (PE+1's old bot); new top from smem (PE-1's old top), PE0 keeps top
            #pragma unroll
            for (int t = 0; t < 4; t++) tb[t] = ii[t];
            if (pe >= 2) {
                const float2* S = (const float2*)(W + (size_t)(stage + pe - 1) * PITCH);
                ta[0] = S[l16]; ta[1] = S[16 + l16]; ta[2] = S[32 + l16];
                ta[3] = g3 ? S[48 + l16] : make_float2(0.f, 0.f);
            }
        } else {
            // new top = intra-in (PE-1's old top / PE0's old bot); new bot from smem (PE+1's old bot), PE49: own old top
            #pragma unroll
            for (int t = 0; t < 4; t++) ta[t] = ii[t];
            if (pe <= 47) {
                const float2* S = (const float2*)(W + (size_t)(stage + pe + 1) * PITCH);
                tb[0] = S[l16]; tb[1] = S[16 + l16]; tb[2] = S[32 + l16];
                tb[3] = g3 ? S[48 + l16] : make_float2(0.f, 0.f);
            } else {
                #pragma unroll
                for (int t = 0; t < 4; t++) tb[t] = sv[t];
            }
        }
    }
    __syncthreads();   // all staging reads done before writeback reuses W

    // writeback: ring is identity after each 99-round sweep -> PE holds rows (pe, 50+pe)
    {
        float2* Rp = (float2*)(W + (size_t)pe * PITCH);
        float2* Rq = (float2*)(W + (size_t)(50 + pe) * PITCH);
        Rp[l16] = ta[0]; Rp[16 + l16] = ta[1]; Rp[32 + l16] = ta[2];
        Rq[l16] = tb[0]; Rq[16 + l16] = tb[1]; Rq[32 + l16] = tb[2];
        if (g3) { Rp[48 + l16] = ta[3]; Rq[48 + l16] = tb[3]; }
    }
    __syncthreads();

    // f_k = log(clip(lambda_k, 1e-6)) / lambda_k^2 ; one row per half-warp
    const int hw = pe;
    for (int k = hw; k < SPD; k += 50) {
        const float* Wk = W + k * PITCH;
        float d = 0.f;
        for (int t = l16; t < SPD; t += 16) d += Wk[t] * Wk[t];
        #pragma unroll
        for (int k2 = 8; k2 >= 1; k2 >>= 1) d += __shfl_xor_sync(0xffffffffu, d, k2, 16);
        if (l16 == 0) {
            float lam = sqrtf(d);
            lwf[k] = logf(fmaxf(lam, 1e-6f)) / fmaxf(d, 1e-12f);
        }
    }
    __syncthreads();
    for (int idx = tid; idx < SPD * SPD; idx += JT) {
        int k = idx / SPD, i = idx % SPD;
        G[k * PITCH + i] = W[k * PITCH + i] * lwf[k];
    }
    __syncthreads();
    const float SQ2 = 1.41421356237309515f;
    for (int u = tid; u < NFLAT; u += JT) {
        float uf = (float)u;
        int i = (int)((201.f - sqrtf(201.f * 201.f - 8.f * uf)) * 0.5f);
        if (i < 0) i = 0; if (i > SPD - 1) i = SPD - 1;
        while (i > 0 && i * (201 - i) / 2 > u) i--;
        while (i < SPD - 1 && (i + 1) * (201 - (i + 1)) / 2 <= u) i++;
        int j = i + (u - i * (201 - i) / 2);
        float dot = 0.f;
        for (int k = 0; k < SPD; k++) dot += G[k * PITCH + i] * W[k * PITCH + j];
        out_flat[(size_t)b * NFLAT + u] = dot * ((i == j) ? 1.f : SQ2);
    }
}

// ---------------- K10: logits = flat @ w_fc^T + b_fc ----------------
__global__ void k_fc(const float* __restrict__ w_fc, const float* __restrict__ b_fc,
                     const float* __restrict__ flat, float* __restrict__ logits) {
    __shared__ float red[256];
    int b = blockIdx.x, tid = threadIdx.x;
    for (int o = 0; o < NCLS; o++) {
        float s = 0.f;
        for (int u = tid; u < NFLAT; u += 256)
            s += flat[(size_t)b * NFLAT + u] * w_fc[(size_t)o * NFLAT + u];
        red[tid] = s; __syncthreads();
        for (int st = 128; st > 0; st >>= 1) { if (tid < st) red[tid] += red[tid + st]; __syncthreads(); }
        if (tid == 0) logits[b * NCLS + o] = red[0] + b_fc[o];
        __syncthreads();
    }
}

// ---------------- launch ----------------
extern "C" void kernel_launch(void* const* d_in, const int* in_sizes, int n_in,
                              void* d_out, int out_size) {
    const float* x = (const float*)d_in[0];
    const int base[3] = {1, 10, 19};
    for (int seg = 0; seg < 3; seg++) {
        k_prep<<<1, 256>>>((const float*)d_in[base[seg] + 0],
                           (const float*)d_in[base[seg] + 1],
                           (const float*)d_in[base[seg] + 2],
                           (const float*)d_in[base[seg] + 3], seg);
    }
    k_gemm1<<<dim3(8, Bz, 3), 128>>>(x);
    k_tail<<<Bz * C3, 256>>>(
        (const float*)d_in[5],  (const float*)d_in[6],  (const float*)d_in[7],  (const float*)d_in[8],  (const float*)d_in[9],
        (const float*)d_in[14], (const float*)d_in[15], (const float*)d_in[16], (const float*)d_in[17], (const float*)d_in[18],
        (const float*)d_in[23], (const float*)d_in[24], (const float*)d_in[25], (const float*)d_in[26], (const float*)d_in[27]);
    k_sconv<<<dim3(8, Bz), 512>>>((const float*)d_in[28]);
    k_mean<<<Bz * SPD, 256>>>();
    k_cov<<<dim3(4, 4, Bz), 256>>>();
    k_aff1<<<dim3(Bz, 40), 256>>>((const float*)d_in[29]);
    k_aff2<<<dim3(Bz, 40), 256>>>((const float*)d_in[29]);

    size_t smemj = (size_t)(2 * SPD * PITCH + 128) * sizeof(float);
    cudaFuncSetAttribute(k_jacobi, cudaFuncAttributeMaxDynamicSharedMemorySize, (int)smemj);
    float* out = (float*)d_out;
    k_jacobi<<<Bz, JT, smemj>>>(out + Bz * NCLS);
    k_fc<<<Bz, 256>>>((const float*)d_in[30], (const float*)d_in[31],
                      (const float*)out + Bz * NCLS, out);
}

// round 15
// speedup vs baseline: 1.6577x; 1.6577x over previous
#include <cuda_runtime.h>
#include <math.h>

#define Bz   16
#define CN   22
#define T    1000
#define EXPD 300
#define FCH  150
#define C3   450
#define SPD  100
#define NCLS 4
#define NFLAT 5050
#define PITCH 102     // float2-aligned row pitch; cols 100,101 are zero pad
#define NSWEEP 9
#define HALO 40
#define JT   800      // 50 half-warps, all active

// ---------------- scratch (device globals; no runtime alloc) ----------------
__device__ float g_W[C3 * CN];
__device__ float g_H1[Bz * C3 * T];
__device__ float g_H2[Bz * C3 * T];
__device__ float g_S[Bz * SPD * T];
__device__ float g_mean[Bz * SPD];
__device__ float g_cov[Bz * SPD * SPD];
__device__ float g_tmp[Bz * SPD * SPD];
__device__ float g_P[Bz * SPD * SPD];

// ---------------- K1: fused parallel prep — block (f, seg) computes 22 weights ----------------
__global__ void k_prep_all(
    const float* __restrict__ w1_0, const float* __restrict__ w2_0, const float* __restrict__ w3_0, const float* __restrict__ w4_0,
    const float* __restrict__ w1_1, const float* __restrict__ w2_1, const float* __restrict__ w3_1, const float* __restrict__ w4_1,
    const float* __restrict__ w1_2, const float* __restrict__ w2_2, const float* __restrict__ w3_2, const float* __restrict__ w4_2)
{
    __shared__ float scale[EXPD];
    __shared__ float part[CN * 12];    // c * 12 + chunk (11 chunks, pad 12)
    __shared__ float A1h[CN + 2];      // halo-padded combined row
    int f   = blockIdx.x;              // 0..FCH-1
    int seg = blockIdx.y;              // 0..2
    const float *w1, *w2, *w3, *w4;
    if (seg == 0)      { w1 = w1_0; w2 = w2_0; w3 = w3_0; w4 = w4_0; }
    else if (seg == 1) { w1 = w1_1; w2 = w2_1; w3 = w3_1; w4 = w4_1; }
    else               { w1 = w1_2; w2 = w2_2; w3 = w3_2; w4 = w4_2; }
    int tid = threadIdx.x;             // 256

    for (int e = tid; e < EXPD; e += 256) {
        float s = 0.f;
        #pragma unroll
        for (int c = 0; c < CN; c++) { float v = w3[e * CN + c]; s += v * v; }
        scale[e] = w2[e] * fminf(1.0f, 1.0f / (sqrtf(s) + 1e-12f));
    }
    __syncthreads();

    const int NCH = 11;
    int c = tid / NCH, chunk = tid % NCH;    // 242 active threads
    if (c < CN) {
        float s = 0.f;
        for (int e = chunk; e < EXPD; e += NCH)
            s += w4[f * EXPD + e] * scale[e] * w3[e * CN + c];
        part[c * 12 + chunk] = s;
    }
    __syncthreads();
    if (tid < CN) {
        float s = 0.f;
        #pragma unroll
        for (int k = 0; k < NCH; k++) s += part[tid * 12 + k];
        A1h[tid + 1] = s;
    }
    if (tid == 0) { A1h[0] = 0.f; A1h[CN + 1] = 0.f; }
    __syncthreads();
    if (tid < CN) {
        // coeff of x[cp]: w1[0]*A1[cp+1] + w1[1]*A1[cp] + w1[2]*A1[cp-1]  (halo -> +1 shift)
        float s = w1[0] * A1h[tid + 2] + w1[1] * A1h[tid + 1] + w1[2] * A1h[tid];
        g_W[(seg * FCH + f) * CN + tid] = s;
    }
}

// ---------------- K2: H1 = Wstack(450x22) @ x per batch (f-split x3) ----------------
__global__ void k_gemm1(const float* __restrict__ x) {
    __shared__ float sW[FCH * CN];
    int tx = threadIdx.x;
    int b  = blockIdx.y;
    int f0 = blockIdx.z * FCH;
    int t  = blockIdx.x * 128 + tx;
    for (int idx = tx; idx < FCH * CN; idx += 128) sW[idx] = g_W[f0 * CN + idx];
    float xr[CN];
    #pragma unroll
    for (int c = 0; c < CN; c++)
        xr[c] = (t < T) ? x[((size_t)b * CN + c) * T + t] : 0.f;
    __syncthreads();
    if (t < T) {
        for (int f = 0; f < FCH; f++) {
            const float* w = &sW[f * CN];
            float a0 = 0.f, a1 = 0.f;
            #pragma unroll
            for (int c = 0; c < CN; c += 2) { a0 += w[c] * xr[c]; a1 += w[c + 1] * xr[c + 1]; }
            g_H1[((size_t)b * C3 + f0 + f) * T + t] = a0 + a1;
        }
    }
}

// ---------------- K3: fused LN -> depthwise temporal conv -> LN per row ----------------
__global__ void k_tail(
    const float* g1_0, const float* b1_0, const float* w5_0, const float* g2_0, const float* b2_0,
    const float* g1_1, const float* b1_1, const float* w5_1, const float* g2_1, const float* b2_1,
    const float* g1_2, const float* b1_2, const float* w5_2, const float* g2_2, const float* b2_2)
{
    __shared__ float buf1[T + 2 * HALO];
    __shared__ float buf2[T];
    __shared__ float sw5[80];
    __shared__ float redA[256], redB[256];
    __shared__ float s_mean, s_rstd;
    int row = blockIdx.x;
    int ch  = row % C3;
    int seg = ch / FCH, fl = ch % FCH;
    const float *g1, *b1, *w5, *g2, *b2; int K;
    if (seg == 0)      { g1 = g1_0; b1 = b1_0; w5 = w5_0; g2 = g2_0; b2 = b2_0; K = 15; }
    else if (seg == 1) { g1 = g1_1; b1 = b1_1; w5 = w5_1; g2 = g2_1; b2 = b2_1; K = 75; }
    else               { g1 = g1_2; b1 = b1_2; w5 = w5_2; g2 = g2_2; b2 = b2_2; K = 55; }
    const float* in = g_H1 + (size_t)row * T;
    float* out = g_H2 + (size_t)row * T;
    int tid = threadIdx.x;

    if (tid < HALO) { buf1[tid] = 0.f; buf1[T + HALO + tid] = 0.f; }
    float s = 0.f, s2 = 0.f;
    for (int t = tid; t < T; t += 256) { float v = in[t]; buf1[HALO + t] = v; s += v; s2 += v * v; }
    redA[tid] = s; redB[tid] = s2; __syncthreads();
    for (int st = 128; st > 0; st >>= 1) {
        if (tid < st) { redA[tid] += redA[tid + st]; redB[tid] += redB[tid + st]; }
        __syncthreads();
    }
    if (tid == 0) {
        float m = redA[0] * (1.f / T); s_mean = m;
        s_rstd = rsqrtf(redB[0] * (1.f / T) - m * m + 1e-5f);
    }
    if (tid < K) sw5[tid] = w5[fl * K + tid];
    __syncthreads();
    float m = s_mean, r = s_rstd;
    for (int t = tid; t < T; t += 256) buf1[HALO + t] = (buf1[HALO + t] - m) * r * g1[t] + b1[t];
    __syncthreads();
    int pad = K / 2;
    for (int t = tid; t < T; t += 256) {
        float acc = 0.f;
        const float* src = &buf1[HALO + t - pad];
        for (int k = 0; k < K; k++) acc += src[k] * sw5[k];
        buf2[t] = acc;
    }
    __syncthreads();
    s = 0.f; s2 = 0.f;
    for (int t = tid; t < T; t += 256) { float v = buf2[t]; s += v; s2 += v * v; }
    redA[tid] = s; redB[tid] = s2; __syncthreads();
    for (int st = 128; st > 0; st >>= 1) {
        if (tid < st) { redA[tid] += redA[tid + st]; redB[tid] += redB[tid + st]; }
        __syncthreads();
    }
    if (tid == 0) {
        float mm = redA[0] * (1.f / T); s_mean = mm;
        s_rstd = rsqrtf(redB[0] * (1.f / T) - mm * mm + 1e-5f);
    }
    __syncthreads();
    m = s_mean; r = s_rstd;
    for (int t = tid; t < T; t += 256) out[t] = (buf2[t] - m) * r * g2[t] + b2[t];
}

// ---------------- K4: S = w_sconv(100x450) @ H2 per batch ----------------
__global__ void k_sconv(const float* __restrict__ w_sconv) {
    __shared__ float sH[45 * 128];
    __shared__ float sW[SPD * 45];
    int tid = threadIdx.x;
    int tx = tid & 127, ig = tid >> 7;
    int t0 = blockIdx.x * 128, b = blockIdx.y;
    float acc[25];
    #pragma unroll
    for (int ii = 0; ii < 25; ii++) acc[ii] = 0.f;
    for (int c0 = 0; c0 < C3; c0 += 45) {
        __syncthreads();
        for (int idx = tid; idx < 45 * 128; idx += 512) {
            int rr = idx >> 7, tt = idx & 127;
            sH[idx] = (t0 + tt < T) ? g_H2[((size_t)b * C3 + c0 + rr) * T + t0 + tt] : 0.f;
        }
        for (int idx = tid; idx < SPD * 45; idx += 512) {
            int i = idx / 45, c = idx % 45;
            sW[idx] = w_sconv[i * C3 + c0 + c];
        }
        __syncthreads();
        for (int c = 0; c < 45; c++) {
            float xv = sH[c * 128 + tx];
            #pragma unroll
            for (int ii = 0; ii < 25; ii++)
                acc[ii] += sW[(ig * 25 + ii) * 45 + c] * xv;
        }
    }
    int t = t0 + tx;
    if (t < T)
        for (int ii = 0; ii < 25; ii++)
            g_S[((size_t)b * SPD + ig * 25 + ii) * T + t] = acc[ii];
}

// ---------------- K5: per-row means of S ----------------
__global__ void k_mean() {
    __shared__ float red[256];
    int row = blockIdx.x;
    const float* in = g_S + (size_t)row * T;
    int tid = threadIdx.x;
    float s = 0.f;
    for (int t = tid; t < T; t += 256) s += in[t];
    red[tid] = s; __syncthreads();
    for (int st = 128; st > 0; st >>= 1) { if (tid < st) red[tid] += red[tid + st]; __syncthreads(); }
    if (tid == 0) g_mean[row] = red[0] * (1.f / T);
}

// ---------------- K6: covariance (tiled SYRK + mean correction + ridge) ----------------
__global__ void k_cov() {
    __shared__ float sA[32 * 51], sB[32 * 51];
    int b = blockIdx.z;
    int it = blockIdx.x * 32, jt = blockIdx.y * 32;
    int tid = threadIdx.x;
    int il = tid >> 4, jl = tid & 15;
    float acc00 = 0.f, acc01 = 0.f, acc10 = 0.f, acc11 = 0.f;
    for (int t0 = 0; t0 < T; t0 += 50) {
        __syncthreads();
        for (int idx = tid; idx < 32 * 50; idx += 256) {
            int rr = idx / 50, tt = idx % 50;
            int gi = it + rr;
            sA[rr * 51 + tt] = (gi < SPD) ? g_S[((size_t)b * SPD + gi) * T + t0 + tt] : 0.f;
            int gj = jt + rr;
            sB[rr * 51 + tt] = (gj < SPD) ? g_S[((size_t)b * SPD + gj) * T + t0 + tt] : 0.f;
        }
        __syncthreads();
        for (int tt = 0; tt < 50; tt++) {
            float a0 = sA[(il * 2) * 51 + tt], a1 = sA[(il * 2 + 1) * 51 + tt];
            float b0 = sB[(jl * 2) * 51 + tt], b1 = sB[(jl * 2 + 1) * 51 + tt];
            acc00 += a0 * b0; acc01 += a0 * b1; acc10 += a1 * b0; acc11 += a1 * b1;
        }
    }
    float accs[2][2] = {{acc00, acc01}, {acc10, acc11}};
    for (int di = 0; di < 2; di++)
        for (int dj = 0; dj < 2; dj++) {
            int i = it + il * 2 + di, j = jt + jl * 2 + dj;
            if (i < SPD && j < SPD) {
                float v = (accs[di][dj] - (float)T * g_mean[b * SPD + i] * g_mean[b * SPD + j]) * (1.f / (T - 1));
                if (i == j) v += 1e-4f;
                g_cov[((size_t)b * SPD + i) * SPD + j] = v;
            }
        }
}

// ---------------- K7/K8: affine congruence P = W C W^T ----------------
__global__ void k_aff1(const float* __restrict__ w_aff) {
    int b = blockIdx.x;
    int o = blockIdx.y * 256 + threadIdx.x;
    if (o >= SPD * SPD) return;
    int i = o / SPD, k = o % SPD;
    float s = 0.f;
    for (int j = 0; j < SPD; j++) s += w_aff[i * SPD + j] * g_cov[((size_t)b * SPD + j) * SPD + k];
    g_tmp[(size_t)b * SPD * SPD + o] = s;
}
__global__ void k_aff2(const float* __restrict__ w_aff) {
    int b = blockIdx.x;
    int o = blockIdx.y * 256 + threadIdx.x;
    if (o >= SPD * SPD) return;
    int i = o / SPD, l = o % SPD;
    float s = 0.f;
    for (int k = 0; k < SPD; k++) s += g_tmp[((size_t)b * SPD + i) * SPD + k] * w_aff[l * SPD + k];
    g_P[(size_t)b * SPD * SPD + o] = s;
}

// ---------------- K9: one-sided Jacobi (Hestenes), float2 rows, 2-reduction rotation ----------------
__global__ __launch_bounds__(JT, 1) void k_jacobi(float* __restrict__ out_flat) {
    extern __shared__ float sh[];
    float* W   = sh;                       // SPD*PITCH
    float* G   = W + SPD * PITCH;          // SPD*PITCH
    float* lwf = G + SPD * PITCH;          // 128
    int b = blockIdx.x, tid = threadIdx.x;
    const int hw  = tid >> 4;              // half-warp id 0..49
    const int l16 = tid & 15;

    for (int idx = tid; idx < SPD * SPD; idx += JT) {
        int i = idx / SPD, j = idx % SPD;
        W[i * PITCH + j] = g_P[(size_t)b * SPD * SPD + idx];
    }
    for (int k = tid; k < SPD; k += JT) {   // zero pad cols 100,101
        W[k * PITCH + 100] = 0.f;
        W[k * PITCH + 101] = 0.f;
    }
    __syncthreads();

    for (int sweep = 0; sweep < NSWEEP; sweep++) {
        for (int rnd = 0; rnd < SPD - 1; rnd++) {
            int p, q;
            if (hw == 0) { p = SPD - 1; q = rnd; }
            else {
                p = (rnd + hw) % (SPD - 1);
                q = (rnd - hw + (SPD - 1)) % (SPD - 1);
            }
            if (p > q) { int t_ = p; p = q; q = t_; }
            float2* Wp2 = (float2*)(W + p * PITCH);
            float2* Wq2 = (float2*)(W + q * PITCH);
            const bool g3 = (l16 < 3);       // 51 float2/row: 16+16+16 + 3 (incl. zero pad)
            float2 wp[4], wq[4];
            wp[0] = Wp2[l16];       wq[0] = Wq2[l16];
            wp[1] = Wp2[16 + l16];  wq[1] = Wq2[16 + l16];
            wp[2] = Wp2[32 + l16];  wq[2] = Wq2[32 + l16];
            if (g3) { wp[3] = Wp2[48 + l16]; wq[3] = Wq2[48 + l16]; }
            else    { wp[3] = make_float2(0.f, 0.f); wq[3] = make_float2(0.f, 0.f); }

            // Only two reduced quantities needed: diff = dqq - dpp, and dpq.
            float diff = 0.f, dpq = 0.f;
            #pragma unroll
            for (int t = 0; t < 4; t++) {
                diff += (wq[t].x * wq[t].x - wp[t].x * wp[t].x)
                      + (wq[t].y * wq[t].y - wp[t].y * wp[t].y);
                dpq  += wp[t].x * wq[t].x + wp[t].y * wq[t].y;
            }
            #pragma unroll
            for (int k = 8; k >= 1; k >>= 1) {
                diff += __shfl_xor_sync(0xffffffffu, diff, k, 16);
                dpq  += __shfl_xor_sync(0xffffffffu, dpq, k, 16);
            }
            if (fabsf(dpq) > 1e-30f) {
                float tau = diff / (2.f * dpq);
                float tt = ((tau >= 0.f) ? 1.f : -1.f) / (fabsf(tau) + sqrtf(1.f + tau * tau));
                float c = rsqrtf(1.f + tt * tt), s = tt * c;
                #pragma unroll
                for (int t = 0; t < 4; t++) {
                    float2 np, nq;
                    np.x = c * wp[t].x - s * wq[t].x; np.y = c * wp[t].y - s * wq[t].y;
                    nq.x = s * wp[t].x + c * wq[t].x; nq.y = s * wp[t].y + c * wq[t].y;
                    wp[t] = np; wq[t] = nq;
                }
                Wp2[l16]      = wp[0];  Wq2[l16]      = wq[0];
                Wp2[16 + l16] = wp[1];  Wq2[16 + l16] = wq[1];
                Wp2[32 + l16] = wp[2];  Wq2[32 + l16] = wq[2];
                if (g3) { Wp2[48 + l16] = wp[3]; Wq2[48 + l16] = wq[3]; }
            }
            __syncthreads();
        }
    }

    // f_k = log(clip(lambda_k, 1e-6)) / lambda_k^2 ; one row per half-warp
    for (int k = hw; k < SPD; k += 50) {
        const float* Wk = W + k * PITCH;
        float d = 0.f;
        for (int t = l16; t < SPD; t += 16) d += Wk[t] * Wk[t];
        #pragma unroll
        for (int k2 = 8; k2 >= 1; k2 >>= 1) d += __shfl_xor_sync(0xffffffffu, d, k2, 16);
        if (l16 == 0) {
            float lam = sqrtf(d);
            lwf[k] = logf(fmaxf(lam, 1e-6f)) / fmaxf(d, 1e-12f);
        }
    }
    __syncthreads();
    for (int idx = tid; idx < SPD * SPD; idx += JT) {
        int k = idx / SPD, i = idx % SPD;
        G[k * PITCH + i] = W[k * PITCH + i] * lwf[k];
    }
    __syncthreads();
    const float SQ2 = 1.41421356237309515f;
    for (int u = tid; u < NFLAT; u += JT) {
        float uf = (float)u;
        int i = (int)((201.f - sqrtf(201.f * 201.f - 8.f * uf)) * 0.5f);
        if (i < 0) i = 0; if (i > SPD - 1) i = SPD - 1;
        while (i > 0 && i * (201 - i) / 2 > u) i--;
        while (i < SPD - 1 && (i + 1) * (201 - (i + 1)) / 2 <= u) i++;
        int j = i + (u - i * (201 - i) / 2);
        float dot = 0.f;
        for (int k = 0; k < SPD; k++) dot += G[k * PITCH + i] * W[k * PITCH + j];
        out_flat[(size_t)b * NFLAT + u] = dot * ((i == j) ? 1.f : SQ2);
    }
}

// ---------------- K10: logits = flat @ w_fc^T + b_fc ----------------
__global__ void k_fc(const float* __restrict__ w_fc, const float* __restrict__ b_fc,
                     const float* __restrict__ flat, float* __restrict__ logits) {
    __shared__ float red[256];
    int b = blockIdx.x, tid = threadIdx.x;
    for (int o = 0; o < NCLS; o++) {
        float s = 0.f;
        for (int u = tid; u < NFLAT; u += 256)
            s += flat[(size_t)b * NFLAT + u] * w_fc[(size_t)o * NFLAT + u];
        red[tid] = s; __syncthreads();
        for (int st = 128; st > 0; st >>= 1) { if (tid < st) red[tid] += red[tid + st]; __syncthreads(); }
        if (tid == 0) logits[b * NCLS + o] = red[0] + b_fc[o];
        __syncthreads();
    }
}

// ---------------- launch ----------------
extern "C" void kernel_launch(void* const* d_in, const int* in_sizes, int n_in,
                              void* d_out, int out_size) {
    const float* x = (const float*)d_in[0];
    k_prep_all<<<dim3(FCH, 3), 256>>>(
        (const float*)d_in[1],  (const float*)d_in[2],  (const float*)d_in[3],  (const float*)d_in[4],
        (const float*)d_in[10], (const float*)d_in[11], (const float*)d_in[12], (const float*)d_in[13],
        (const float*)d_in[19], (const float*)d_in[20], (const float*)d_in[21], (const float*)d_in[22]);
    k_gemm1<<<dim3(8, Bz, 3), 128>>>(x);
    k_tail<<<Bz * C3, 256>>>(
        (const float*)d_in[5],  (const float*)d_in[6],  (const float*)d_in[7],  (const float*)d_in[8],  (const float*)d_in[9],
        (const float*)d_in[14], (const float*)d_in[15], (const float*)d_in[16], (const float*)d_in[17], (const float*)d_in[18],
        (const float*)d_in[23], (const float*)d_in[24], (const float*)d_in[25], (const float*)d_in[26], (const float*)d_in[27]);
    k_sconv<<<dim3(8, Bz), 512>>>((const float*)d_in[28]);
    k_mean<<<Bz * SPD, 256>>>();
    k_cov<<<dim3(4, 4, Bz), 256>>>();
    k_aff1<<<dim3(Bz, 40), 256>>>((const float*)d_in[29]);
    k_aff2<<<dim3(Bz, 40), 256>>>((const float*)d_in[29]);

    size_t smemj = (size_t)(2 * SPD * PITCH + 128) * sizeof(float);
    cudaFuncSetAttribute(k_jacobi, cudaFuncAttributeMaxDynamicSharedMemorySize, (int)smemj);
    float* out = (float*)d_out;
    k_jacobi<<<Bz, JT, smemj>>>(out + Bz * NCLS);
    k_fc<<<Bz, 256>>>((const float*)d_in[30], (const float*)d_in[31],
                      (const float*)out + Bz * NCLS, out);
}

// round 17
// speedup vs baseline: 1.7464x; 1.0535x over previous
#include <cuda_runtime.h>
#include <math.h>

#define Bz   16
#define CN   22
#define T    1000
#define EXPD 300
#define FCH  150
#define C3   450
#define SPD  100
#define NCLS 4
#define NFLAT 5050
#define PITCH 102     // float2-aligned row pitch; cols 100,101 are zero pad
#define NSWEEP 9
#define HALO 40
#define JT   800      // 50 half-warps, all active

// ---------------- scratch (device globals; no runtime alloc) ----------------
__device__ float g_W[C3 * CN];
__device__ float g_H1[Bz * C3 * T];
__device__ float g_H2[Bz * C3 * T];
__device__ float g_S[Bz * SPD * T];
__device__ float g_mean[Bz * SPD];
__device__ float g_cov[Bz * SPD * SPD];
__device__ float g_tmp[Bz * SPD * SPD];
__device__ float g_P[Bz * SPD * SPD];

// ---------------- K1: fused parallel prep — block (f, seg) computes 22 weights ----------------
__global__ void k_prep_all(
    const float* __restrict__ w1_0, const float* __restrict__ w2_0, const float* __restrict__ w3_0, const float* __restrict__ w4_0,
    const float* __restrict__ w1_1, const float* __restrict__ w2_1, const float* __restrict__ w3_1, const float* __restrict__ w4_1,
    const float* __restrict__ w1_2, const float* __restrict__ w2_2, const float* __restrict__ w3_2, const float* __restrict__ w4_2)
{
    __shared__ float scale[EXPD];
    __shared__ float part[CN * 12];    // c * 12 + chunk (11 chunks, pad 12)
    __shared__ float A1h[CN + 2];      // halo-padded combined row
    int f   = blockIdx.x;              // 0..FCH-1
    int seg = blockIdx.y;              // 0..2
    const float *w1, *w2, *w3, *w4;
    if (seg == 0)      { w1 = w1_0; w2 = w2_0; w3 = w3_0; w4 = w4_0; }
    else if (seg == 1) { w1 = w1_1; w2 = w2_1; w3 = w3_1; w4 = w4_1; }
    else               { w1 = w1_2; w2 = w2_2; w3 = w3_2; w4 = w4_2; }
    int tid = threadIdx.x;             // 256

    for (int e = tid; e < EXPD; e += 256) {
        float s = 0.f;
        #pragma unroll
        for (int c = 0; c < CN; c++) { float v = w3[e * CN + c]; s += v * v; }
        scale[e] = w2[e] * fminf(1.0f, 1.0f / (sqrtf(s) + 1e-12f));
    }
    __syncthreads();

    const int NCH = 11;
    int c = tid / NCH, chunk = tid % NCH;    // 242 active threads
    if (c < CN) {
        float s = 0.f;
        for (int e = chunk; e < EXPD; e += NCH)
            s += w4[f * EXPD + e] * scale[e] * w3[e * CN + c];
        part[c * 12 + chunk] = s;
    }
    __syncthreads();
    if (tid < CN) {
        float s = 0.f;
        #pragma unroll
        for (int k = 0; k < NCH; k++) s += part[tid * 12 + k];
        A1h[tid + 1] = s;
    }
    if (tid == 0) { A1h[0] = 0.f; A1h[CN + 1] = 0.f; }
    __syncthreads();
    if (tid < CN) {
        // coeff of x[cp]: w1[0]*A1[cp+1] + w1[1]*A1[cp] + w1[2]*A1[cp-1]  (halo -> +1 shift)
        float s = w1[0] * A1h[tid + 2] + w1[1] * A1h[tid + 1] + w1[2] * A1h[tid];
        g_W[(seg * FCH + f) * CN + tid] = s;
    }
}

// ---------------- K2: H1 = Wstack(450x22) @ x per batch (f-split x3) ----------------
__global__ void k_gemm1(const float* __restrict__ x) {
    __shared__ float sW[FCH * CN];
    int tx = threadIdx.x;
    int b  = blockIdx.y;
    int f0 = blockIdx.z * FCH;
    int t  = blockIdx.x * 128 + tx;
    for (int idx = tx; idx < FCH * CN; idx += 128) sW[idx] = g_W[f0 * CN + idx];
    float xr[CN];
    #pragma unroll
    for (int c = 0; c < CN; c++)
        xr[c] = (t < T) ? x[((size_t)b * CN + c) * T + t] : 0.f;
    __syncthreads();
    if (t < T) {
        for (int f = 0; f < FCH; f++) {
            const float* w = &sW[f * CN];
            float a0 = 0.f, a1 = 0.f;
            #pragma unroll
            for (int c = 0; c < CN; c += 2) { a0 += w[c] * xr[c]; a1 += w[c + 1] * xr[c + 1]; }
            g_H1[((size_t)b * C3 + f0 + f) * T + t] = a0 + a1;
        }
    }
}

// ---------------- K3: fused LN -> depthwise temporal conv -> LN per row ----------------
__global__ void k_tail(
    const float* g1_0, const float* b1_0, const float* w5_0, const float* g2_0, const float* b2_0,
    const float* g1_1, const float* b1_1, const float* w5_1, const float* g2_1, const float* b2_1,
    const float* g1_2, const float* b1_2, const float* w5_2, const float* g2_2, const float* b2_2)
{
    __shared__ float buf1[T + 2 * HALO];
    __shared__ float buf2[T];
    __shared__ float sw5[80];
    __shared__ float redA[256], redB[256];
    __shared__ float s_mean, s_rstd;
    int row = blockIdx.x;
    int ch  = row % C3;
    int seg = ch / FCH, fl = ch % FCH;
    const float *g1, *b1, *w5, *g2, *b2; int K;
    if (seg == 0)      { g1 = g1_0; b1 = b1_0; w5 = w5_0; g2 = g2_0; b2 = b2_0; K = 15; }
    else if (seg == 1) { g1 = g1_1; b1 = b1_1; w5 = w5_1; g2 = g2_1; b2 = b2_1; K = 75; }
    else               { g1 = g1_2; b1 = b1_2; w5 = w5_2; g2 = g2_2; b2 = b2_2; K = 55; }
    const float* in = g_H1 + (size_t)row * T;
    float* out = g_H2 + (size_t)row * T;
    int tid = threadIdx.x;

    if (tid < HALO) { buf1[tid] = 0.f; buf1[T + HALO + tid] = 0.f; }
    float s = 0.f, s2 = 0.f;
    for (int t = tid; t < T; t += 256) { float v = in[t]; buf1[HALO + t] = v; s += v; s2 += v * v; }
    redA[tid] = s; redB[tid] = s2; __syncthreads();
    for (int st = 128; st > 0; st >>= 1) {
        if (tid < st) { redA[tid] += redA[tid + st]; redB[tid] += redB[tid + st]; }
        __syncthreads();
    }
    if (tid == 0) {
        float m = redA[0] * (1.f / T); s_mean = m;
        s_rstd = rsqrtf(redB[0] * (1.f / T) - m * m + 1e-5f);
    }
    if (tid < K) sw5[tid] = w5[fl * K + tid];
    __syncthreads();
    float m = s_mean, r = s_rstd;
    for (int t = tid; t < T; t += 256) buf1[HALO + t] = (buf1[HALO + t] - m) * r * g1[t] + b1[t];
    __syncthreads();
    int pad = K / 2;
    for (int t = tid; t < T; t += 256) {
        float acc = 0.f;
        const float* src = &buf1[HALO + t - pad];
        for (int k = 0; k < K; k++) acc += src[k] * sw5[k];
        buf2[t] = acc;
    }
    __syncthreads();
    s = 0.f; s2 = 0.f;
    for (int t = tid; t < T; t += 256) { float v = buf2[t]; s += v; s2 += v * v; }
    redA[tid] = s; redB[tid] = s2; __syncthreads();
    for (int st = 128; st > 0; st >>= 1) {
        if (tid < st) { redA[tid] += redA[tid + st]; redB[tid] += redB[tid + st]; }
        __syncthreads();
    }
    if (tid == 0) {
        float mm = redA[0] * (1.f / T); s_mean = mm;
        s_rstd = rsqrtf(redB[0] * (1.f / T) - mm * mm + 1e-5f);
    }
    __syncthreads();
    m = s_mean; r = s_rstd;
    for (int t = tid; t < T; t += 256) out[t] = (buf2[t] - m) * r * g2[t] + b2[t];
}

// ---------------- K4: S = w_sconv(100x450) @ H2 — row-split for occupancy ----------------
// grid (8, Bz, 2), 256 threads: tx = t within 128-tile, ig in {0,1} -> 25 rows each;
// blockIdx.z selects row half (50 rows). 256 blocks total.
__global__ void k_sconv(const float* __restrict__ w_sconv) {
    __shared__ float sH[45 * 128];
    __shared__ float sW[50 * 45];
    int tid = threadIdx.x;               // 256
    int tx = tid & 127, ig = tid >> 7;   // ig in {0,1}
    int t0 = blockIdx.x * 128, b = blockIdx.y;
    int r0 = blockIdx.z * 50;            // row base for this block
    float acc[25];
    #pragma unroll
    for (int ii = 0; ii < 25; ii++) acc[ii] = 0.f;
    for (int c0 = 0; c0 < C3; c0 += 45) {
        __syncthreads();
        for (int idx = tid; idx < 45 * 128; idx += 256) {
            int rr = idx >> 7, tt = idx & 127;
            sH[idx] = (t0 + tt < T) ? g_H2[((size_t)b * C3 + c0 + rr) * T + t0 + tt] : 0.f;
        }
        for (int idx = tid; idx < 50 * 45; idx += 256) {
            int i = idx / 45, c = idx % 45;
            sW[idx] = w_sconv[(r0 + i) * C3 + c0 + c];
        }
        __syncthreads();
        for (int c = 0; c < 45; c++) {
            float xv = sH[c * 128 + tx];
            #pragma unroll
            for (int ii = 0; ii < 25; ii++)
                acc[ii] += sW[(ig * 25 + ii) * 45 + c] * xv;
        }
    }
    int t = t0 + tx;
    if (t < T)
        for (int ii = 0; ii < 25; ii++)
            g_S[((size_t)b * SPD + r0 + ig * 25 + ii) * T + t] = acc[ii];
}

// ---------------- K5: per-row means of S ----------------
__global__ void k_mean() {
    __shared__ float red[256];
    int row = blockIdx.x;
    const float* in = g_S + (size_t)row * T;
    int tid = threadIdx.x;
    float s = 0.f;
    for (int t = tid; t < T; t += 256) s += in[t];
    red[tid] = s; __syncthreads();
    for (int st = 128; st > 0; st >>= 1) { if (tid < st) red[tid] += red[tid + st]; __syncthreads(); }
    if (tid == 0) g_mean[row] = red[0] * (1.f / T);
}

// ---------------- K6: covariance (tiled SYRK + mean correction + ridge) ----------------
__global__ void k_cov() {
    __shared__ float sA[32 * 51], sB[32 * 51];
    int b = blockIdx.z;
    int it = blockIdx.x * 32, jt = blockIdx.y * 32;
    int tid = threadIdx.x;
    int il = tid >> 4, jl = tid & 15;
    float acc00 = 0.f, acc01 = 0.f, acc10 = 0.f, acc11 = 0.f;
    for (int t0 = 0; t0 < T; t0 += 50) {
        __syncthreads();
        for (int idx = tid; idx < 32 * 50; idx += 256) {
            int rr = idx / 50, tt = idx % 50;
            int gi = it + rr;
            sA[rr * 51 + tt] = (gi < SPD) ? g_S[((size_t)b * SPD + gi) * T + t0 + tt] : 0.f;
            int gj = jt + rr;
            sB[rr * 51 + tt] = (gj < SPD) ? g_S[((size_t)b * SPD + gj) * T + t0 + tt] : 0.f;
        }
        __syncthreads();
        for (int tt = 0; tt < 50; tt++) {
            float a0 = sA[(il * 2) * 51 + tt], a1 = sA[(il * 2 + 1) * 51 + tt];
            float b0 = sB[(jl * 2) * 51 + tt], b1 = sB[(jl * 2 + 1) * 51 + tt];
            acc00 += a0 * b0; acc01 += a0 * b1; acc10 += a1 * b0; acc11 += a1 * b1;
        }
    }
    float accs[2][2] = {{acc00, acc01}, {acc10, acc11}};
    for (int di = 0; di < 2; di++)
        for (int dj = 0; dj < 2; dj++) {
            int i = it + il * 2 + di, j = jt + jl * 2 + dj;
            if (i < SPD && j < SPD) {
                float v = (accs[di][dj] - (float)T * g_mean[b * SPD + i] * g_mean[b * SPD + j]) * (1.f / (T - 1));
                if (i == j) v += 1e-4f;
                g_cov[((size_t)b * SPD + i) * SPD + j] = v;
            }
        }
}

// ---------------- K7/K8: affine congruence P = W C W^T ----------------
__global__ void k_aff1(const float* __restrict__ w_aff) {
    int b = blockIdx.x;
    int o = blockIdx.y * 256 + threadIdx.x;
    if (o >= SPD * SPD) return;
    int i = o / SPD, k = o % SPD;
    float s = 0.f;
    for (int j = 0; j < SPD; j++) s += w_aff[i * SPD + j] * g_cov[((size_t)b * SPD + j) * SPD + k];
    g_tmp[(size_t)b * SPD * SPD + o] = s;
}
__global__ void k_aff2(const float* __restrict__ w_aff) {
    int b = blockIdx.x;
    int o = blockIdx.y * 256 + threadIdx.x;
    if (o >= SPD * SPD) return;
    int i = o / SPD, l = o % SPD;
    float s = 0.f;
    for (int k = 0; k < SPD; k++) s += g_tmp[((size_t)b * SPD + i) * SPD + k] * w_aff[l * SPD + k];
    g_P[(size_t)b * SPD * SPD + o] = s;
}

// ---------------- K9: one-sided Jacobi (Hestenes), float2 rows, 2-reduction rotation ----------------
__global__ __launch_bounds__(JT, 1) void k_jacobi(float* __restrict__ out_flat) {
    extern __shared__ float sh[];
    float* W   = sh;                       // SPD*PITCH
    float* G   = W + SPD * PITCH;          // SPD*PITCH
    float* lwf = G + SPD * PITCH;          // 128
    int b = blockIdx.x, tid = threadIdx.x;
    const int hw  = tid >> 4;              // half-warp id 0..49
    const int l16 = tid & 15;

    for (int idx = tid; idx < SPD * SPD; idx += JT) {
        int i = idx / SPD, j = idx % SPD;
        W[i * PITCH + j] = g_P[(size_t)b * SPD * SPD + idx];
    }
    for (int k = tid; k < SPD; k += JT) {   // zero pad cols 100,101
        W[k * PITCH + 100] = 0.f;
        W[k * PITCH + 101] = 0.f;
    }
    __syncthreads();

    for (int sweep = 0; sweep < NSWEEP; sweep++) {
        for (int rnd = 0; rnd < SPD - 1; rnd++) {
            int p, q;
            if (hw == 0) { p = SPD - 1; q = rnd; }
            else {
                p = (rnd + hw) % (SPD - 1);
                q = (rnd - hw + (SPD - 1)) % (SPD - 1);
            }
            if (p > q) { int t_ = p; p = q; q = t_; }
            float2* Wp2 = (float2*)(W + p * PITCH);
            float2* Wq2 = (float2*)(W + q * PITCH);
            const bool g3 = (l16 < 3);       // 51 float2/row: 16+16+16 + 3 (incl. zero pad)
            float2 wp[4], wq[4];
            wp[0] = Wp2[l16];       wq[0] = Wq2[l16];
            wp[1] = Wp2[16 + l16];  wq[1] = Wq2[16 + l16];
            wp[2] = Wp2[32 + l16];  wq[2] = Wq2[32 + l16];
            if (g3) { wp[3] = Wp2[48 + l16]; wq[3] = Wq2[48 + l16]; }
            else    { wp[3] = make_float2(0.f, 0.f); wq[3] = make_float2(0.f, 0.f); }

            // Only two reduced quantities needed: diff = dqq - dpp, and dpq.
            float diff = 0.f, dpq = 0.f;
            #pragma unroll
            for (int t = 0; t < 4; t++) {
                diff += (wq[t].x * wq[t].x - wp[t].x * wp[t].x)
                      + (wq[t].y * wq[t].y - wp[t].y * wp[t].y);
                dpq  += wp[t].x * wq[t].x + wp[t].y * wq[t].y;
            }
            #pragma unroll
            for (int k = 8; k >= 1; k >>= 1) {
                diff += __shfl_xor_sync(0xffffffffu, diff, k, 16);
                dpq  += __shfl_xor_sync(0xffffffffu, dpq, k, 16);
            }
            if (fabsf(dpq) > 1e-30f) {
                float tau = diff / (2.f * dpq);
                float tt = ((tau >= 0.f) ? 1.f : -1.f) / (fabsf(tau) + sqrtf(1.f + tau * tau));
                float c = rsqrtf(1.f + tt * tt), s = tt * c;
                #pragma unroll
                for (int t = 0; t < 4; t++) {
                    float2 np, nq;
                    np.x = c * wp[t].x - s * wq[t].x; np.y = c * wp[t].y - s * wq[t].y;
                    nq.x = s * wp[t].x + c * wq[t].x; nq.y = s * wp[t].y + c * wq[t].y;
                    wp[t] = np; wq[t] = nq;
                }
                Wp2[l16]      = wp[0];  Wq2[l16]      = wq[0];
                Wp2[16 + l16] = wp[1];  Wq2[16 + l16] = wq[1];
                Wp2[32 + l16] = wp[2];  Wq2[32 + l16] = wq[2];
                if (g3) { Wp2[48 + l16] = wp[3]; Wq2[48 + l16] = wq[3]; }
            }
            __syncthreads();
        }
    }

    // f_k = log(clip(lambda_k, 1e-6)) / lambda_k^2 ; one row per half-warp
    for (int k = hw; k < SPD; k += 50) {
        const float* Wk = W + k * PITCH;
        float d = 0.f;
        for (int t = l16; t < SPD; t += 16) d += Wk[t] * Wk[t];
        #pragma unroll
        for (int k2 = 8; k2 >= 1; k2 >>= 1) d += __shfl_xor_sync(0xffffffffu, d, k2, 16);
        if (l16 == 0) {
            float lam = sqrtf(d);
            lwf[k] = logf(fmaxf(lam, 1e-6f)) / fmaxf(d, 1e-12f);
        }
    }
    __syncthreads();
    for (int idx = tid; idx < SPD * SPD; idx += JT) {
        int k = idx / SPD, i = idx % SPD;
        G[k * PITCH + i] = W[k * PITCH + i] * lwf[k];
    }
    __syncthreads();
    const float SQ2 = 1.41421356237309515f;
    for (int u = tid; u < NFLAT; u += JT) {
        float uf = (float)u;
        int i = (int)((201.f - sqrtf(201.f * 201.f - 8.f * uf)) * 0.5f);
        if (i < 0) i = 0; if (i > SPD - 1) i = SPD - 1;
        while (i > 0 && i * (201 - i) / 2 > u) i--;
        while (i < SPD - 1 && (i + 1) * (201 - (i + 1)) / 2 <= u) i++;
        int j = i + (u - i * (201 - i) / 2);
        float dot = 0.f;
        for (int k = 0; k < SPD; k++) dot += G[k * PITCH + i] * W[k * PITCH + j];
        out_flat[(size_t)b * NFLAT + u] = dot * ((i == j) ? 1.f : SQ2);
    }
}

// ---------------- K10: logits = flat @ w_fc^T + b_fc ----------------
__global__ void k_fc(const float* __restrict__ w_fc, const float* __restrict__ b_fc,
                     const float* __restrict__ flat, float* __restrict__ logits) {
    __shared__ float red[256];
    int b = blockIdx.x, tid = threadIdx.x;
    for (int o = 0; o < NCLS; o++) {
        float s = 0.f;
        for (int u = tid; u < NFLAT; u += 256)
            s += flat[(size_t)b * NFLAT + u] * w_fc[(size_t)o * NFLAT + u];
        red[tid] = s; __syncthreads();
        for (int st = 128; st > 0; st >>= 1) { if (tid < st) red[tid] += red[tid + st]; __syncthreads(); }
        if (tid == 0) logits[b * NCLS + o] = red[0] + b_fc[o];
        __syncthreads();
    }
}

// ---------------- launch ----------------
extern "C" void kernel_launch(void* const* d_in, const int* in_sizes, int n_in,
                              void* d_out, int out_size) {
    const float* x = (const float*)d_in[0];
    k_prep_all<<<dim3(FCH, 3), 256>>>(
        (const float*)d_in[1],  (const float*)d_in[2],  (const float*)d_in[3],  (const float*)d_in[4],
        (const float*)d_in[10], (const float*)d_in[11], (const float*)d_in[12], (const float*)d_in[13],
        (const float*)d_in[19], (const float*)d_in[20], (const float*)d_in[21], (const float*)d_in[22]);
    k_gemm1<<<dim3(8, Bz, 3), 128>>>(x);
    k_tail<<<Bz * C3, 256>>>(
        (const float*)d_in[5],  (const float*)d_in[6],  (const float*)d_in[7],  (const float*)d_in[8],  (const float*)d_in[9],
        (const float*)d_in[14], (const float*)d_in[15], (const float*)d_in[16], (const float*)d_in[17], (const float*)d_in[18],
        (const float*)d_in[23], (const float*)d_in[24], (const float*)d_in[25], (const float*)d_in[26], (const float*)d_in[27]);
    k_sconv<<<dim3(8, Bz, 2), 256>>>((const float*)d_in[28]);
    k_mean<<<Bz * SPD, 256>>>();
    k_cov<<<dim3(4, 4, Bz), 256>>>();
    k_aff1<<<dim3(Bz, 40), 256>>>((const float*)d_in[29]);
    k_aff2<<<dim3(Bz, 40), 256>>>((const float*)d_in[29]);

    size_t smemj = (size_t)(2 * SPD * PITCH + 128) * sizeof(float);
    cudaFuncSetAttribute(k_jacobi, cudaFuncAttributeMaxDynamicSharedMemorySize, (int)smemj);
    float* out = (float*)d_out;
    k_jacobi<<<Bz, JT, smemj>>>(out + Bz * NCLS);
    k_fc<<<Bz, 256>>>((const float*)d_in[30], (const float*)d_in[31],
                      (const float*)out + Bz * NCLS, out);
}